// round 9
// baseline (speedup 1.0000x reference)
#include <cuda_runtime.h>
#include <cuda_fp16.h>
#include <math.h>
#include <stdint.h>

#define SEQ     2048
#define HIDDEN  2048
#define HD      128
#define NH      16
#define NKV     2

// ---------------- scratch (device globals) ----------------
__device__ __align__(16) __half g_qh [(size_t)NH  * SEQ * HD];
__device__ __align__(16) __half g_kh [(size_t)NKV * SEQ * HD];
__device__ __align__(16) __half g_vth[(size_t)NKV * HD * SEQ];
__device__ __align__(16) __half g_ah [(size_t)NH  * SEQ * HD];
__device__ __align__(16) float2 g_tab[(size_t)SEQ * 64];   // rope cos/sin table
// packed f16 weights: qw | kw | vw | ow (element offsets)
#define QW_OFF 0
#define KW_OFF 4194304
#define VW_OFF 4718592
#define OW_OFF 5242880
#define W_TOT  9437184
__device__ __align__(16) __half g_wh[W_TOT];

// ================= helpers =================
__device__ __forceinline__ uint32_t smem_u32(const void* p) {
    uint32_t a;
    asm("{ .reg .u64 t; cvta.to.shared.u64 t, %1; cvt.u32.u64 %0, t; }" : "=r"(a) : "l"(p));
    return a;
}

#define LDSM4(r0, r1, r2, r3, addr) \
    asm volatile("ldmatrix.sync.aligned.m8n8.x4.shared.b16 {%0,%1,%2,%3}, [%4];" \
                 : "=r"(r0), "=r"(r1), "=r"(r2), "=r"(r3) : "r"(addr))

#define MMA16816(c, a, b) \
    asm volatile("mma.sync.aligned.m16n8k16.row.col.f32.f16.f16.f32 " \
                 "{%0,%1,%2,%3}, {%4,%5,%6,%7}, {%8,%9}, {%0,%1,%2,%3};" \
                 : "+f"((c)[0]), "+f"((c)[1]), "+f"((c)[2]), "+f"((c)[3]) \
                 : "r"((a)[0]), "r"((a)[1]), "r"((a)[2]), "r"((a)[3]), \
                   "r"((b)[0]), "r"((b)[1]))

#define CPA16(dst, src) \
    asm volatile("cp.async.cg.shared.global [%0], [%1], 16;" :: "r"(dst), "l"(src))
#define CPA_COMMIT()  asm volatile("cp.async.commit_group;")
#define CPA_WAIT0()   asm volatile("cp.async.wait_group 0;")
#define CPA_WAIT1()   asm volatile("cp.async.wait_group 1;")

// ================= projection GEMM (pure f16, 1-term) =================
// per-buffer smem: AH [0,10240), BH [10240,20480)
#define ROWB  80
#define TILEB (128 * ROWB)
#define BUF1  (2 * TILEB)
#define GSMB  (2 * BUF1)

__device__ __forceinline__ void cvt_hi16(const float* __restrict__ xs,
                                         uint32_t* __restrict__ hw)
{
#pragma unroll
    for (int q = 0; q < 8; q++) {
        __half2 h = __floats2half2_rn(xs[2 * q], xs[2 * q + 1]);
        hw[q] = *reinterpret_cast<uint32_t*>(&h);
    }
}

// Warp N-mapping: warp wid&3 covers cols {wn16..wn16+15} u {wn16+64..wn16+79},
// wn16 = (wid&3)*16. acc[mi][ni] col = wn16 + (ni>>1)*64 + (ni&1)*8 + t*2.
// -> RoPE pairs (c, c+64) are thread-local: acc[mi][pr] <-> acc[mi][pr+2].
//
// FUSED (projection): z<NH -> rope -> qh f16; z<NH+NKV -> rope -> kh f16;
//                     else -> transpose via smem -> vth f16.
// !FUSED (O-proj): plain fp32 streaming store.
template<bool AF32, bool FUSED>
__global__ __launch_bounds__(256, 2)
void tgemm(const float* __restrict__ Af0, const __half* __restrict__ Ahg,
           const __half* __restrict__ B0,
           const float* __restrict__ Af1, const __half* __restrict__ B1,
           const float* __restrict__ Af2, const __half* __restrict__ B2,
           float* __restrict__ Cout, int z1, int z2,
           int K, int lda, int ldb, int ldc, long sA, long sB,
           const float2* __restrict__ tab)
{
    extern __shared__ char dsm[];
    const int tid  = threadIdx.x;
    const int wid  = tid >> 5;
    const int lane = tid & 31;
    const int wm   = (wid >> 2) << 6;
    const int wn16 = (wid & 3) << 4;
    const int zorig = blockIdx.z;
    int z          = zorig;
    const int m0   = blockIdx.y << 7;
    const int n0   = blockIdx.x << 7;

    const float*  Afz = Af0;
    const __half* Bz  = B0;
    if (z >= z2)      { Afz = Af2; Bz = B2; z -= z2; }
    else if (z >= z1) { Afz = Af1; Bz = B1; z -= z1; }

    const float*  A  = AF32 ? (Afz + (long)z * sA + (long)m0 * lda) : nullptr;
    const __half* Ah = AF32 ? nullptr : (Ahg + (long)z * sA + (long)m0 * lda);
    const __half* B  = Bz + (long)z * sB + (long)n0 * ldb;

    const int nch  = K >> 5;
    const int lrow = tid >> 1, lhalf = tid & 1;
    const int soff = lrow * ROWB + lhalf * 32;

    float acc[4][4][4];
#pragma unroll
    for (int i = 0; i < 4; i++)
#pragma unroll
        for (int j = 0; j < 4; j++)
#pragma unroll
            for (int q = 0; q < 4; q++) acc[i][j][q] = 0.f;

    const uint32_t smbase = smem_u32(dsm);
    const int a_row  = wm + (lane & 15);
    const int a_koff = (lane >> 4) << 4;
    const int brow   = (lane & 7) + ((lane >> 4) & 1) * 8;
    const int b_koff = ((lane >> 3) & 1) << 4;

    const uint32_t cp_off  = (uint32_t)lrow * ROWB + (uint32_t)lhalf * 32;
    const long     cp_srcb = (long)lrow * ldb + lhalf * 16;
    const long     cp_srca = (long)lrow * lda + lhalf * 16;

    float ra[16];
    // ---- prologue: chunk 0 ----
    {
        CPA16(smbase + TILEB + cp_off,      B + cp_srcb);
        CPA16(smbase + TILEB + cp_off + 16, B + cp_srcb + 8);
        if (AF32) {
            const float4* pa = (const float4*)(A + (long)lrow * lda + lhalf * 16);
#pragma unroll
            for (int q = 0; q < 4; q++) *(float4*)(ra + 4 * q) = __ldcs(pa + q);
            uint32_t hw[8];
            cvt_hi16(ra, hw);
            *(uint4*)(dsm + soff)      = make_uint4(hw[0], hw[1], hw[2], hw[3]);
            *(uint4*)(dsm + soff + 16) = make_uint4(hw[4], hw[5], hw[6], hw[7]);
        } else {
            CPA16(smbase + cp_off,      Ah + cp_srca);
            CPA16(smbase + cp_off + 16, Ah + cp_srca + 8);
        }
        CPA_COMMIT();
        CPA_WAIT0();
    }
    __syncthreads();

    for (int i = 0; i < nch; i++) {
        if (i + 1 < nch) {
            const int k0 = (i + 1) << 5;
            const uint32_t bb = smbase + ((i + 1) & 1) * BUF1;
            CPA16(bb + TILEB + cp_off,      B + k0 + cp_srcb);
            CPA16(bb + TILEB + cp_off + 16, B + k0 + cp_srcb + 8);
            if (AF32) {
                const float4* pa = (const float4*)(A + (long)lrow * lda + k0 + lhalf * 16);
#pragma unroll
                for (int q = 0; q < 4; q++) *(float4*)(ra + 4 * q) = __ldcs(pa + q);
            } else {
                CPA16(bb + cp_off,      Ah + k0 + cp_srca);
                CPA16(bb + cp_off + 16, Ah + k0 + cp_srca + 8);
            }
            CPA_COMMIT();
        }
        const uint32_t tb = smbase + (i & 1) * BUF1;
#pragma unroll
        for (int ks = 0; ks < 2; ks++) {
            uint32_t bh[4][2];
            const uint32_t ka = ks * 32 + a_koff;
            const uint32_t kb = ks * 32 + b_koff;
#pragma unroll
            for (int p = 0; p < 2; p++) {
                uint32_t r0, r1, r2, r3;
                LDSM4(r0, r1, r2, r3,
                      tb + TILEB + (uint32_t)(wn16 + p * 64 + brow) * ROWB + kb);
                bh[2 * p][0] = r0; bh[2 * p][1] = r1;
                bh[2 * p + 1][0] = r2; bh[2 * p + 1][1] = r3;
            }
#pragma unroll
            for (int mi = 0; mi < 4; mi++) {
                uint32_t ah[4];
                LDSM4(ah[0], ah[1], ah[2], ah[3],
                      tb + (uint32_t)(a_row + mi * 16) * ROWB + ka);
#pragma unroll
                for (int ni = 0; ni < 4; ni++) MMA16816(acc[mi][ni], ah, bh[ni]);
            }
        }
        if (i + 1 < nch) {
            if (AF32) {
                char* buf = dsm + ((i + 1) & 1) * BUF1;
                uint32_t hw[8];
                cvt_hi16(ra, hw);
                *(uint4*)(buf + soff)      = make_uint4(hw[0], hw[1], hw[2], hw[3]);
                *(uint4*)(buf + soff + 16) = make_uint4(hw[4], hw[5], hw[6], hw[7]);
            }
            CPA_WAIT0();
        }
        __syncthreads();
    }

    // ---------------- epilogue ----------------
    const int g = lane >> 2, t = lane & 3;

    if (!FUSED) {
        // O projection: fp32 streaming stores
        float* C = Cout + (long)zorig * (long)SEQ * HIDDEN;
#pragma unroll
        for (int mi = 0; mi < 4; mi++) {
            const int r0 = m0 + wm + mi * 16 + g;
#pragma unroll
            for (int ni = 0; ni < 4; ni++) {
                const int cc = n0 + wn16 + (ni >> 1) * 64 + (ni & 1) * 8 + t * 2;
                __stcs((float2*)(C + (long)r0 * ldc + cc),
                       make_float2(acc[mi][ni][0], acc[mi][ni][1]));
                __stcs((float2*)(C + (long)(r0 + 8) * ldc + cc),
                       make_float2(acc[mi][ni][2], acc[mi][ni][3]));
            }
        }
        return;
    }

    if (zorig < NH + NKV) {
        // ---- RoPE + f16 store (q or k) ----
        __half* qhp; __half* khp;
        asm("{ .reg .u64 t; cvta.global.u64 t, 0; }" ::);  // no-op keepalive
        {
            // resolve destinations from globals
        }
        __half* dst = (zorig < NH)
            ? (g_qh + (long)zorig * SEQ * HD)
            : (g_kh + (long)(zorig - NH) * SEQ * HD);
#pragma unroll
        for (int mi = 0; mi < 4; mi++) {
            const int l0 = m0 + wm + mi * 16 + g;
#pragma unroll
            for (int pr = 0; pr < 2; pr++) {
                const int i0 = wn16 + pr * 8 + t * 2;   // 0..63
#pragma unroll
                for (int rr = 0; rr < 2; rr++) {
                    const int l = l0 + rr * 8;
                    const int e = rr * 2;
                    const float2 cs0 = tab[l * 64 + i0];
                    const float2 cs1 = tab[l * 64 + i0 + 1];
                    const float x1a = acc[mi][pr][e],     x1b = acc[mi][pr][e + 1];
                    const float x2a = acc[mi][pr + 2][e], x2b = acc[mi][pr + 2][e + 1];
                    const float y1a = x1a * cs0.x - x2a * cs0.y;
                    const float y1b = x1b * cs1.x - x2b * cs1.y;
                    const float y2a = x2a * cs0.x + x1a * cs0.y;
                    const float y2b = x2b * cs1.x + x1b * cs1.y;
                    *(__half2*)(dst + (long)l * HD + i0)      = __floats2half2_rn(y1a, y1b);
                    *(__half2*)(dst + (long)l * HD + i0 + 64) = __floats2half2_rn(y2a, y2b);
                }
            }
        }
    } else {
        // ---- V: transpose via smem, f16 store to vth ----
        __half* sm = (__half*)dsm;     // [128 cols][136]
#pragma unroll
        for (int mi = 0; mi < 4; mi++) {
            const int r0 = wm + mi * 16 + g;
#pragma unroll
            for (int ni = 0; ni < 4; ni++) {
                const int cc = wn16 + (ni >> 1) * 64 + (ni & 1) * 8 + t * 2;
                sm[cc * 136 + r0]           = __float2half_rn(acc[mi][ni][0]);
                sm[(cc + 1) * 136 + r0]     = __float2half_rn(acc[mi][ni][1]);
                sm[cc * 136 + r0 + 8]       = __float2half_rn(acc[mi][ni][2]);
                sm[(cc + 1) * 136 + r0 + 8] = __float2half_rn(acc[mi][ni][3]);
            }
        }
        __syncthreads();
        __half* dst = g_vth + (long)(zorig - NH - NKV) * HD * SEQ;
        const int col = tid >> 1, rh = (tid & 1) << 6;
        const __half* src = sm + col * 136 + rh;
        __half* gp = dst + (long)col * SEQ + m0 + rh;
#pragma unroll
        for (int q = 0; q < 8; q++)
            *(uint4*)(gp + q * 8) = *(const uint4*)(src + q * 8);
    }
}

// ================= flash attention: pure f16, 64 Q rows / CTA, 128 threads =================
// smem: QH [0,17408), K bufs [17408,+17408x2), VT bufs [52224,+18432x2)  total 89088
#define K_OFF  17408
#define KBUFB  17408
#define V_OFF  52224
#define VBUFB  18432
#define FSMEM  89088
#define FC     0.12751744f   // log2(e) / sqrt(128)

__device__ __forceinline__ void kv_prefetch(uint32_t smb, int buf, int kv0,
    const __half* __restrict__ khp, const __half* __restrict__ vhp, int tid)
{
#pragma unroll
    for (int i = 0; i < 8; i++) {
        int t = tid + (i << 7);
        int unit = t & 15, row = t >> 4;            // 0..63
        CPA16(smb + K_OFF + buf * KBUFB + row * 272 + unit * 16,
              khp + (long)(kv0 + row) * HD + unit * 8);
    }
#pragma unroll
    for (int i = 0; i < 8; i++) {
        int t = tid + (i << 7);
        int unit = t & 7, row = t >> 3;             // 0..127
        CPA16(smb + V_OFF + buf * VBUFB + row * 144 + unit * 16,
              vhp + (long)row * SEQ + kv0 + unit * 8);
    }
}

__global__ __launch_bounds__(128, 2)
void flash_k(const __half* __restrict__ qhg, const __half* __restrict__ khg,
             const __half* __restrict__ vhg, __half* __restrict__ oah)
{
    extern __shared__ char dsm[];
    const uint32_t smb = smem_u32(dsm);
    const int tid  = threadIdx.x;
    const int w    = tid >> 5;
    const int lane = tid & 31;
    const int z    = blockIdx.x;
    const int mb   = 31 - blockIdx.y;     // heavy blocks first
    const int kvh  = z >> 3;
    const int m0   = mb << 6;
    const int nt   = mb + 1;

    const __half* qhp = qhg + ((long)z * SEQ + m0) * HD;
    const __half* khp = khg + (long)kvh * SEQ * HD;
    const __half* vhp = vhg + (long)kvh * HD * SEQ;

    // Q -> smem (one-time): 64 rows x 8 16B-units
#pragma unroll
    for (int i = 0; i < 8; i++) {
        int t = tid + (i << 7);
        int unit = t & 15, row = t >> 4;
        CPA16(smb + row * 272 + unit * 16, qhp + (long)row * HD + unit * 8);
    }
    CPA_COMMIT();
    kv_prefetch(smb, 0, 0, khp, vhp, tid);
    CPA_COMMIT();

    // wait for Q, hoist Q fragments to registers
    CPA_WAIT1();
    __syncthreads();
    const uint32_t qa_h = smb + (uint32_t)((w << 4) + (lane & 15)) * 272 + ((lane >> 4) << 4);
    uint32_t qf[8][4];
#pragma unroll
    for (int j = 0; j < 8; j++)
        LDSM4(qf[j][0], qf[j][1], qf[j][2], qf[j][3], qa_h + j * 32);

    float o[16][4];
#pragma unroll
    for (int nb = 0; nb < 16; nb++)
#pragma unroll
        for (int q = 0; q < 4; q++) o[nb][q] = 0.f;
    float mr0 = -1e30f, mr1 = -1e30f, l0 = 0.f, l1 = 0.f;

    const int wrow = m0 + (w << 4);
    const uint32_t brow = (lane & 7) + ((lane >> 4) & 1) * 8;
    const uint32_t bko  = ((lane >> 3) & 1) << 4;

    int buf = 0;
    for (int it = 0; it < nt; it++) {
        if (it + 1 < nt) {
            kv_prefetch(smb, buf ^ 1, (it + 1) << 6, khp, vhp, tid);
            CPA_COMMIT();
            CPA_WAIT1();
        } else {
            CPA_WAIT0();
        }
        __syncthreads();

        const int kv0 = it << 6;
        {
            const uint32_t kb_h = smb + K_OFF + buf * KBUFB;
            const uint32_t vb_h = smb + V_OFF + buf * VBUFB;

            float s[8][4];
#pragma unroll
            for (int nb = 0; nb < 8; nb++)
#pragma unroll
                for (int q = 0; q < 4; q++) s[nb][q] = 0.f;

            // ---- scores: s = Q . K^T ----
#pragma unroll
            for (int j = 0; j < 8; j++) {
#pragma unroll
                for (int g16 = 0; g16 < 4; g16++) {
                    uint32_t bh[4];
                    const uint32_t ba = (uint32_t)(g16 * 16 + brow) * 272 + bko + j * 32;
                    LDSM4(bh[0], bh[1], bh[2], bh[3], kb_h + ba);
                    MMA16816(s[2 * g16],     qf[j], bh);
                    MMA16816(s[2 * g16 + 1], qf[j], bh + 2);
                }
            }

            // ---- causal mask ----
            const int r0 = wrow + (lane >> 2);
            const int c0 = kv0 + ((lane & 3) << 1);
            if (kv0 + 63 > wrow) {
#pragma unroll
                for (int nb = 0; nb < 8; nb++) {
                    const int c = c0 + nb * 8;
                    if (c     > r0    ) s[nb][0] = -1e30f;
                    if (c + 1 > r0    ) s[nb][1] = -1e30f;
                    if (c     > r0 + 8) s[nb][2] = -1e30f;
                    if (c + 1 > r0 + 8) s[nb][3] = -1e30f;
                }
            }

            // ---- online softmax ----
            float tm0 = -1e30f, tm1 = -1e30f;
#pragma unroll
            for (int nb = 0; nb < 8; nb++) {
                tm0 = fmaxf(tm0, fmaxf(s[nb][0], s[nb][1]));
                tm1 = fmaxf(tm1, fmaxf(s[nb][2], s[nb][3]));
            }
            tm0 = fmaxf(tm0, __shfl_xor_sync(0xffffffffu, tm0, 1));
            tm0 = fmaxf(tm0, __shfl_xor_sync(0xffffffffu, tm0, 2));
            tm1 = fmaxf(tm1, __shfl_xor_sync(0xffffffffu, tm1, 1));
            tm1 = fmaxf(tm1, __shfl_xor_sync(0xffffffffu, tm1, 2));
            const float mn0 = fmaxf(mr0, tm0), mn1 = fmaxf(mr1, tm1);
            const float sf0 = exp2f((mr0 - mn0) * FC);
            const float sf1 = exp2f((mr1 - mn1) * FC);
            mr0 = mn0; mr1 = mn1;
            l0 *= sf0;  l1 *= sf1;
#pragma unroll
            for (int nb = 0; nb < 16; nb++) {
                o[nb][0] *= sf0; o[nb][1] *= sf0;
                o[nb][2] *= sf1; o[nb][3] *= sf1;
            }
            float rs0 = 0.f, rs1 = 0.f;
#pragma unroll
            for (int nb = 0; nb < 8; nb++) {
                s[nb][0] = exp2f((s[nb][0] - mn0) * FC); rs0 += s[nb][0];
                s[nb][1] = exp2f((s[nb][1] - mn0) * FC); rs0 += s[nb][1];
                s[nb][2] = exp2f((s[nb][2] - mn1) * FC); rs1 += s[nb][2];
                s[nb][3] = exp2f((s[nb][3] - mn1) * FC); rs1 += s[nb][3];
            }
            rs0 += __shfl_xor_sync(0xffffffffu, rs0, 1);
            rs0 += __shfl_xor_sync(0xffffffffu, rs0, 2);
            rs1 += __shfl_xor_sync(0xffffffffu, rs1, 1);
            rs1 += __shfl_xor_sync(0xffffffffu, rs1, 2);
            l0 += rs0; l1 += rs1;

            // ---- PV: o += P . V ----
#pragma unroll
            for (int j = 0; j < 4; j++) {
                uint32_t pha[4];
#pragma unroll
                for (int hq = 0; hq < 4; hq++) {
                    const int nb = 2 * j + (hq >> 1);
                    const int e  = (hq & 1) << 1;
                    __half2 h = __floats2half2_rn(s[nb][e], s[nb][e + 1]);
                    pha[hq] = *reinterpret_cast<uint32_t*>(&h);
                }
#pragma unroll
                for (int g16 = 0; g16 < 8; g16++) {
                    uint32_t bh[4];
                    const uint32_t ba = (uint32_t)(g16 * 16 + brow) * 144 + bko + j * 32;
                    LDSM4(bh[0], bh[1], bh[2], bh[3], vb_h + ba);
                    MMA16816(o[2 * g16],     pha, bh);
                    MMA16816(o[2 * g16 + 1], pha, bh + 2);
                }
            }
        }
        __syncthreads();
        buf ^= 1;
    }

    // ---- epilogue: normalize, f16 ----
    const float inv0 = 1.f / l0, inv1 = 1.f / l1;
    const int r0 = wrow + (lane >> 2);
    const long base0 = ((long)z * SEQ + r0) * HD + ((lane & 3) << 1);
    const long base1 = base0 + 8 * HD;
#pragma unroll
    for (int nb = 0; nb < 16; nb++) {
        *(__half2*)(oah + base0 + nb * 8) =
            __floats2half2_rn(o[nb][0] * inv0, o[nb][1] * inv0);
        *(__half2*)(oah + base1 + nb * 8) =
            __floats2half2_rn(o[nb][2] * inv1, o[nb][3] * inv1);
    }
}

// ---------------- RoPE table: cos/sin per (l, i) ----------------
__global__ __launch_bounds__(256)
void rope_table(const int* __restrict__ pos, float2* __restrict__ tab)
{
    int idx = blockIdx.x * 256 + threadIdx.x;
    if (idx >= SEQ * 64) return;
    int i = idx & 63;
    int l = idx >> 6;

    float invf = exp2f(-(float)i * 0.31143075889569023f);
    float ang  = (float)pos[l] * invf;
    float q  = rintf(ang * 0.15915494309189535f);
    float r  = ang - q * 6.28125f;
    r        = r   - q * 1.9353071795864769e-3f;
    float s, c;
    sincosf(r, &s, &c);
    tab[idx] = make_float2(c, s);
}

// ---------------- fp32 -> f16 all weights in one launch ----------------
__global__ __launch_bounds__(256)
void cvt16_all(const float* __restrict__ qw, const float* __restrict__ kw,
               const float* __restrict__ vw, const float* __restrict__ ow,
               __half* __restrict__ d)
{
    int e = (blockIdx.x * 256 + threadIdx.x) << 2;
    if (e >= W_TOT) return;
    const float* s;
    if      (e < KW_OFF) s = qw + e;
    else if (e < VW_OFF) s = kw + (e - KW_OFF);
    else if (e < OW_OFF) s = vw + (e - VW_OFF);
    else                 s = ow + (e - OW_OFF);
    float4 v = *(const float4*)s;
    ((__half2*)(d + e))[0] = __floats2half2_rn(v.x, v.y);
    ((__half2*)(d + e))[1] = __floats2half2_rn(v.z, v.w);
}

// ---------------- launch ----------------
extern "C" void kernel_launch(void* const* d_in, const int* in_sizes, int n_in,
                              void* d_out, int out_size)
{
    const float* qhid = (const float*)d_in[0];
    const float* khid = (const float*)d_in[1];
    const float* vhid = (const float*)d_in[2];
    const int*   pos  = (const int*)  d_in[4];
    const float* qw   = (const float*)d_in[5];
    const float* kw   = (const float*)d_in[6];
    const float* vw   = (const float*)d_in[7];
    const float* ow   = (const float*)d_in[8];
    float*       out  = (float*)d_out;

    __half *qhh, *khh, *vth, *ahh, *wh;
    float2* tab;
    cudaGetSymbolAddress((void**)&qhh, g_qh);
    cudaGetSymbolAddress((void**)&khh, g_kh);
    cudaGetSymbolAddress((void**)&vth, g_vth);
    cudaGetSymbolAddress((void**)&ahh, g_ah);
    cudaGetSymbolAddress((void**)&wh,  g_wh);
    cudaGetSymbolAddress((void**)&tab, g_tab);

    cudaFuncSetAttribute(tgemm<true,  true >, cudaFuncAttributeMaxDynamicSharedMemorySize, GSMB);
    cudaFuncSetAttribute(tgemm<false, false>, cudaFuncAttributeMaxDynamicSharedMemorySize, GSMB);
    cudaFuncSetAttribute(flash_k,             cudaFuncAttributeMaxDynamicSharedMemorySize, FSMEM);

    const long HH  = (long)SEQ * HIDDEN;
    const long HDW = (long)HD * HIDDEN;

    // rope table + f16 weights
    rope_table<<<(SEQ * 64 + 255) / 256, 256>>>(pos, tab);
    cvt16_all<<<(W_TOT / 4 + 255) / 256, 256>>>(qw, kw, vw, ow, wh);

    // Q+K+V projections, fused RoPE / transpose / f16 epilogues, ONE launch
    tgemm<true, true><<<dim3(1, 16, NH + 2 * NKV), 256, GSMB>>>(
        qhid, nullptr, wh + QW_OFF,
        khid, wh + KW_OFF,
        vhid, wh + VW_OFF,
        nullptr, NH, NH + NKV,
        HIDDEN, HIDDEN, HIDDEN, HD, HH, HDW, tab);

    // fused attention -> attn f16
    flash_k<<<dim3(NH, 32), 128, FSMEM>>>(qhh, khh, vth, ahh);

    // O projection: A = attn f16, B = ow f16 (per-head offset z*128)
    tgemm<false, false><<<dim3(16, 16, NH), 256, GSMB>>>(
        nullptr, ahh, wh + OW_OFF,
        nullptr, nullptr,
        nullptr, nullptr,
        out, 99, 99,
        HD, HD, HIDDEN, HIDDEN, (long)SEQ * HD, (long)HD, nullptr);
}

// round 10
// speedup vs baseline: 1.1232x; 1.1232x over previous
#include <cuda_runtime.h>
#include <cuda_fp16.h>
#include <math.h>
#include <stdint.h>

#define SEQ     2048
#define HIDDEN  2048
#define HD      128
#define NH      16
#define NKV     2

// ---------------- scratch (device globals) ----------------
__device__ __align__(16) __half g_qh [(size_t)NH  * SEQ * HD];
__device__ __align__(16) __half g_kh [(size_t)NKV * SEQ * HD];
__device__ __align__(16) __half g_vth[(size_t)NKV * HD * SEQ];
__device__ __align__(16) __half g_ah [(size_t)NH  * SEQ * HD];
__device__ __align__(16) float2 g_tab[(size_t)SEQ * 64];
#define QW_OFF 0
#define KW_OFF 4194304
#define VW_OFF 4718592
#define OW_OFF 5242880
#define W_TOT  9437184
__device__ __align__(16) __half g_wh[W_TOT];

// ================= helpers =================
__device__ __forceinline__ uint32_t smem_u32(const void* p) {
    uint32_t a;
    asm("{ .reg .u64 t; cvta.to.shared.u64 t, %1; cvt.u32.u64 %0, t; }" : "=r"(a) : "l"(p));
    return a;
}

#define LDSM4(r0, r1, r2, r3, addr) \
    asm volatile("ldmatrix.sync.aligned.m8n8.x4.shared.b16 {%0,%1,%2,%3}, [%4];" \
                 : "=r"(r0), "=r"(r1), "=r"(r2), "=r"(r3) : "r"(addr))

#define MMA16816(c, a, b) \
    asm volatile("mma.sync.aligned.m16n8k16.row.col.f32.f16.f16.f32 " \
                 "{%0,%1,%2,%3}, {%4,%5,%6,%7}, {%8,%9}, {%0,%1,%2,%3};" \
                 : "+f"((c)[0]), "+f"((c)[1]), "+f"((c)[2]), "+f"((c)[3]) \
                 : "r"((a)[0]), "r"((a)[1]), "r"((a)[2]), "r"((a)[3]), \
                   "r"((b)[0]), "r"((b)[1]))

#define CPA16(dst, src) \
    asm volatile("cp.async.cg.shared.global [%0], [%1], 16;" :: "r"(dst), "l"(src))
#define CPA_COMMIT()  asm volatile("cp.async.commit_group;")
#define CPA_WAIT0()   asm volatile("cp.async.wait_group 0;")
#define CPA_WAIT1()   asm volatile("cp.async.wait_group 1;")

// ================= fused Q/K/V projection: M-tile 64, K-chunk 32 =================
// per-buffer smem: AH [0,5120), BH [5120,15360); double buffered
#define ROWB   80
#define ATILE  5120
#define PBUF   15360
#define PSMB   (2 * PBUF)

__device__ __forceinline__ void cvt_hi8(const float* __restrict__ xs,
                                        uint32_t* __restrict__ hw)
{
#pragma unroll
    for (int q = 0; q < 4; q++) {
        __half2 h = __floats2half2_rn(xs[2 * q], xs[2 * q + 1]);
        hw[q] = *reinterpret_cast<uint32_t*>(&h);
    }
}

// z<NH: Q head -> rope -> g_qh; z<NH+NKV: K -> rope -> g_kh; else V -> transpose -> g_vth.
// Warp layout: 8 warps = 2M(32 rows) x 4N; warp cols {wn16..+15} u {wn16+64..+79}
// so RoPE pairs (c, c+64) are thread-local (acc[mi][pr] <-> acc[mi][pr+2]).
__global__ __launch_bounds__(256, 2)
void proj_k(const float* __restrict__ qhid, const float* __restrict__ khid,
            const float* __restrict__ vhid, const __half* __restrict__ wh,
            const float2* __restrict__ tab)
{
    extern __shared__ char dsm[];
    const int tid  = threadIdx.x;
    const int wid  = tid >> 5;
    const int lane = tid & 31;
    const int wm   = (wid >> 2) << 5;      // 0 / 32
    const int wn16 = (wid & 3) << 4;
    const int zorig = blockIdx.z;
    const int m0   = blockIdx.y << 6;      // 64-row tiles

    const float*  A;
    const __half* B;
    if (zorig < NH)            { A = qhid + (long)zorig * SEQ * HIDDEN; B = wh + QW_OFF; }
    else if (zorig < NH + NKV) { A = khid + (long)(zorig - NH) * SEQ * HIDDEN; B = wh + KW_OFF + (long)(zorig - NH) * HD * HIDDEN; }
    else                       { A = vhid + (long)(zorig - NH - NKV) * SEQ * HIDDEN; B = wh + VW_OFF + (long)(zorig - NH - NKV) * HD * HIDDEN; }
    if (zorig < NH) B += (long)zorig * HD * HIDDEN;
    A += (long)m0 * HIDDEN;

    float acc[2][4][4];
#pragma unroll
    for (int i = 0; i < 2; i++)
#pragma unroll
        for (int j = 0; j < 4; j++)
#pragma unroll
            for (int q = 0; q < 4; q++) acc[i][j][q] = 0.f;

    const uint32_t smbase = smem_u32(dsm);
    const int a_row  = wm + (lane & 15);
    const int a_koff = (lane >> 4) << 4;
    const int brow   = (lane & 7) + ((lane >> 4) & 1) * 8;
    const int b_koff = ((lane >> 3) & 1) << 4;

    // loader mappings
    const int arow = tid >> 2, aunit = tid & 3;           // A: 64 rows x 4 units
    const int asoff = arow * ROWB + aunit * 16;
    const int br_   = tid >> 1, bhalf = tid & 1;          // B: 128 rows x 2x16B
    const uint32_t bcp_off = ATILE + (uint32_t)br_ * ROWB + (uint32_t)bhalf * 32;
    const long     bcp_src = (long)br_ * HIDDEN + bhalf * 16;

    float ra[8];
    // ---- prologue: chunk 0 ----
    {
        CPA16(smbase + bcp_off,      B + bcp_src);
        CPA16(smbase + bcp_off + 16, B + bcp_src + 8);
        const float4* pa = (const float4*)(A + (long)arow * HIDDEN + aunit * 8);
        *(float4*)(ra)     = __ldcs(pa);
        *(float4*)(ra + 4) = __ldcs(pa + 1);
        uint32_t hw[4];
        cvt_hi8(ra, hw);
        *(uint4*)(dsm + asoff) = make_uint4(hw[0], hw[1], hw[2], hw[3]);
        CPA_COMMIT();
        CPA_WAIT0();
    }
    __syncthreads();

    for (int i = 0; i < 64; i++) {
        if (i + 1 < 64) {
            const int k0 = (i + 1) << 5;
            const uint32_t bb = smbase + ((i + 1) & 1) * PBUF;
            CPA16(bb + bcp_off,      B + k0 + bcp_src);
            CPA16(bb + bcp_off + 16, B + k0 + bcp_src + 8);
            const float4* pa = (const float4*)(A + (long)arow * HIDDEN + k0 + aunit * 8);
            *(float4*)(ra)     = __ldcs(pa);
            *(float4*)(ra + 4) = __ldcs(pa + 1);
            CPA_COMMIT();
        }
        const uint32_t tb = smbase + (i & 1) * PBUF;
#pragma unroll
        for (int ks = 0; ks < 2; ks++) {
            uint32_t bh[4][2];
            const uint32_t ka = ks * 32 + a_koff;
            const uint32_t kb = ks * 32 + b_koff;
#pragma unroll
            for (int p = 0; p < 2; p++) {
                uint32_t r0, r1, r2, r3;
                LDSM4(r0, r1, r2, r3,
                      tb + ATILE + (uint32_t)(wn16 + p * 64 + brow) * ROWB + kb);
                bh[2 * p][0] = r0; bh[2 * p][1] = r1;
                bh[2 * p + 1][0] = r2; bh[2 * p + 1][1] = r3;
            }
#pragma unroll
            for (int mi = 0; mi < 2; mi++) {
                uint32_t ah[4];
                LDSM4(ah[0], ah[1], ah[2], ah[3],
                      tb + (uint32_t)(a_row + mi * 16) * ROWB + ka);
#pragma unroll
                for (int ni = 0; ni < 4; ni++) MMA16816(acc[mi][ni], ah, bh[ni]);
            }
        }
        if (i + 1 < 64) {
            char* buf = dsm + ((i + 1) & 1) * PBUF;
            uint32_t hw[4];
            cvt_hi8(ra, hw);
            *(uint4*)(buf + asoff) = make_uint4(hw[0], hw[1], hw[2], hw[3]);
            CPA_WAIT0();
        }
        __syncthreads();
    }

    // ---------------- epilogue ----------------
    const int g = lane >> 2, t = lane & 3;

    if (zorig < NH + NKV) {
        // RoPE + f16 store
        __half* dst = (zorig < NH)
            ? (g_qh + (long)zorig * SEQ * HD)
            : (g_kh + (long)(zorig - NH) * SEQ * HD);
#pragma unroll
        for (int mi = 0; mi < 2; mi++) {
            const int l0 = m0 + wm + mi * 16 + g;
#pragma unroll
            for (int pr = 0; pr < 2; pr++) {
                const int i0 = wn16 + pr * 8 + t * 2;
#pragma unroll
                for (int rr = 0; rr < 2; rr++) {
                    const int l = l0 + rr * 8;
                    const int e = rr * 2;
                    const float2 cs0 = tab[l * 64 + i0];
                    const float2 cs1 = tab[l * 64 + i0 + 1];
                    const float x1a = acc[mi][pr][e],     x1b = acc[mi][pr][e + 1];
                    const float x2a = acc[mi][pr + 2][e], x2b = acc[mi][pr + 2][e + 1];
                    *(__half2*)(dst + (long)l * HD + i0) =
                        __floats2half2_rn(x1a * cs0.x - x2a * cs0.y,
                                          x1b * cs1.x - x2b * cs1.y);
                    *(__half2*)(dst + (long)l * HD + i0 + 64) =
                        __floats2half2_rn(x2a * cs0.x + x1a * cs0.y,
                                          x2b * cs1.x + x1b * cs1.y);
                }
            }
        }
    } else {
        // V: transpose via smem -> vth f16 (smem as [128 cols][72])
        __half* sm = (__half*)dsm;
#pragma unroll
        for (int mi = 0; mi < 2; mi++) {
            const int r0 = wm + mi * 16 + g;
#pragma unroll
            for (int ni = 0; ni < 4; ni++) {
                const int cc = wn16 + (ni >> 1) * 64 + (ni & 1) * 8 + t * 2;
                sm[cc * 72 + r0]           = __float2half_rn(acc[mi][ni][0]);
                sm[(cc + 1) * 72 + r0]     = __float2half_rn(acc[mi][ni][1]);
                sm[cc * 72 + r0 + 8]       = __float2half_rn(acc[mi][ni][2]);
                sm[(cc + 1) * 72 + r0 + 8] = __float2half_rn(acc[mi][ni][3]);
            }
        }
        __syncthreads();
        __half* dst = g_vth + (long)(zorig - NH - NKV) * HD * SEQ;
        const int col = tid >> 1, rh = (tid & 1) << 5;
        const __half* src = sm + col * 72 + rh;
        __half* gp = dst + (long)col * SEQ + m0 + rh;
#pragma unroll
        for (int q = 0; q < 4; q++)
            *(uint4*)(gp + q * 8) = *(const uint4*)(src + q * 8);
    }
}

// ================= O projection: one-shot K=128 =================
// smem: A [0,34816), B [34816,69632)   (272B row stride)
#define OROW  272
#define OASZ  34816
#define OSMB  69632

__global__ __launch_bounds__(256, 2)
void oproj_k(const __half* __restrict__ ahh, const __half* __restrict__ whO,
             float* __restrict__ out)
{
    extern __shared__ char dsm[];
    const int tid  = threadIdx.x;
    const int wid  = tid >> 5;
    const int lane = tid & 31;
    const int wm   = (wid >> 2) << 6;
    const int wn   = (wid & 3) << 5;
    const int z    = blockIdx.z;
    const int m0   = blockIdx.y << 7;
    const int n0   = blockIdx.x << 7;

    const __half* A = ahh + ((long)z * SEQ + m0) * HD;
    const __half* B = whO + (long)n0 * HIDDEN + (long)z * HD;
    float*        C = out + (long)z * SEQ * HIDDEN;

    const uint32_t smbase = smem_u32(dsm);

    // load full A and B tiles (128 x 128 f16 each): 2048 units apiece
#pragma unroll
    for (int i = 0; i < 8; i++) {
        const int u = tid + (i << 8);
        const int row = u >> 4, un = u & 15;
        CPA16(smbase + row * OROW + un * 16, A + (long)row * HD + un * 8);
        CPA16(smbase + OASZ + row * OROW + un * 16, B + (long)row * HIDDEN + un * 8);
    }
    CPA_COMMIT();
    CPA_WAIT0();
    __syncthreads();

    float acc[4][4][4];
#pragma unroll
    for (int i = 0; i < 4; i++)
#pragma unroll
        for (int j = 0; j < 4; j++)
#pragma unroll
            for (int q = 0; q < 4; q++) acc[i][j][q] = 0.f;

    const int a_row  = wm + (lane & 15);
    const int a_koff = (lane >> 4) << 4;
    const int brow   = (lane & 7) + ((lane >> 4) & 1) * 8;
    const int b_koff = ((lane >> 3) & 1) << 4;

#pragma unroll
    for (int ks = 0; ks < 8; ks++) {
        uint32_t bh[4][2];
        const uint32_t ka = ks * 32 + a_koff;
        const uint32_t kb = ks * 32 + b_koff;
#pragma unroll
        for (int p = 0; p < 2; p++) {
            uint32_t r0, r1, r2, r3;
            LDSM4(r0, r1, r2, r3,
                  smbase + OASZ + (uint32_t)(wn + p * 16 + brow) * OROW + kb);
            bh[2 * p][0] = r0; bh[2 * p][1] = r1;
            bh[2 * p + 1][0] = r2; bh[2 * p + 1][1] = r3;
        }
#pragma unroll
        for (int mi = 0; mi < 4; mi++) {
            uint32_t ah[4];
            LDSM4(ah[0], ah[1], ah[2], ah[3],
                  smbase + (uint32_t)(a_row + mi * 16) * OROW + ka);
#pragma unroll
            for (int ni = 0; ni < 4; ni++) MMA16816(acc[mi][ni], ah, bh[ni]);
        }
    }

    const int g = lane >> 2, t = lane & 3;
#pragma unroll
    for (int mi = 0; mi < 4; mi++) {
        const int r0 = m0 + wm + mi * 16 + g;
#pragma unroll
        for (int ni = 0; ni < 4; ni++) {
            const int cc = n0 + wn + ni * 8 + t * 2;
            __stcs((float2*)(C + (long)r0 * HIDDEN + cc),
                   make_float2(acc[mi][ni][0], acc[mi][ni][1]));
            __stcs((float2*)(C + (long)(r0 + 8) * HIDDEN + cc),
                   make_float2(acc[mi][ni][2], acc[mi][ni][3]));
        }
    }
}

// ================= flash attention (unchanged from R8/R9, validated) =================
#define K_OFF  17408
#define KBUFB  17408
#define V_OFF  52224
#define VBUFB  18432
#define FSMEM  89088
#define FC     0.12751744f

__device__ __forceinline__ void kv_prefetch(uint32_t smb, int buf, int kv0,
    const __half* __restrict__ khp, const __half* __restrict__ vhp, int tid)
{
#pragma unroll
    for (int i = 0; i < 8; i++) {
        int t = tid + (i << 7);
        int unit = t & 15, row = t >> 4;
        CPA16(smb + K_OFF + buf * KBUFB + row * 272 + unit * 16,
              khp + (long)(kv0 + row) * HD + unit * 8);
    }
#pragma unroll
    for (int i = 0; i < 8; i++) {
        int t = tid + (i << 7);
        int unit = t & 7, row = t >> 3;
        CPA16(smb + V_OFF + buf * VBUFB + row * 144 + unit * 16,
              vhp + (long)row * SEQ + kv0 + unit * 8);
    }
}

__global__ __launch_bounds__(128, 2)
void flash_k(const __half* __restrict__ qhg, const __half* __restrict__ khg,
             const __half* __restrict__ vhg, __half* __restrict__ oah)
{
    extern __shared__ char dsm[];
    const uint32_t smb = smem_u32(dsm);
    const int tid  = threadIdx.x;
    const int w    = tid >> 5;
    const int lane = tid & 31;
    const int z    = blockIdx.x;
    const int mb   = 31 - blockIdx.y;
    const int kvh  = z >> 3;
    const int m0   = mb << 6;
    const int nt   = mb + 1;

    const __half* qhp = qhg + ((long)z * SEQ + m0) * HD;
    const __half* khp = khg + (long)kvh * SEQ * HD;
    const __half* vhp = vhg + (long)kvh * HD * SEQ;

#pragma unroll
    for (int i = 0; i < 8; i++) {
        int t = tid + (i << 7);
        int unit = t & 15, row = t >> 4;
        CPA16(smb + row * 272 + unit * 16, qhp + (long)row * HD + unit * 8);
    }
    CPA_COMMIT();
    kv_prefetch(smb, 0, 0, khp, vhp, tid);
    CPA_COMMIT();

    CPA_WAIT1();
    __syncthreads();
    const uint32_t qa_h = smb + (uint32_t)((w << 4) + (lane & 15)) * 272 + ((lane >> 4) << 4);
    uint32_t qf[8][4];
#pragma unroll
    for (int j = 0; j < 8; j++)
        LDSM4(qf[j][0], qf[j][1], qf[j][2], qf[j][3], qa_h + j * 32);

    float o[16][4];
#pragma unroll
    for (int nb = 0; nb < 16; nb++)
#pragma unroll
        for (int q = 0; q < 4; q++) o[nb][q] = 0.f;
    float mr0 = -1e30f, mr1 = -1e30f, l0 = 0.f, l1 = 0.f;

    const int wrow = m0 + (w << 4);
    const uint32_t brow = (lane & 7) + ((lane >> 4) & 1) * 8;
    const uint32_t bko  = ((lane >> 3) & 1) << 4;

    int buf = 0;
    for (int it = 0; it < nt; it++) {
        if (it + 1 < nt) {
            kv_prefetch(smb, buf ^ 1, (it + 1) << 6, khp, vhp, tid);
            CPA_COMMIT();
            CPA_WAIT1();
        } else {
            CPA_WAIT0();
        }
        __syncthreads();

        const int kv0 = it << 6;
        {
            const uint32_t kb_h = smb + K_OFF + buf * KBUFB;
            const uint32_t vb_h = smb + V_OFF + buf * VBUFB;

            float s[8][4];
#pragma unroll
            for (int nb = 0; nb < 8; nb++)
#pragma unroll
                for (int q = 0; q < 4; q++) s[nb][q] = 0.f;

#pragma unroll
            for (int j = 0; j < 8; j++) {
#pragma unroll
                for (int g16 = 0; g16 < 4; g16++) {
                    uint32_t bh[4];
                    const uint32_t ba = (uint32_t)(g16 * 16 + brow) * 272 + bko + j * 32;
                    LDSM4(bh[0], bh[1], bh[2], bh[3], kb_h + ba);
                    MMA16816(s[2 * g16],     qf[j], bh);
                    MMA16816(s[2 * g16 + 1], qf[j], bh + 2);
                }
            }

            const int r0 = wrow + (lane >> 2);
            const int c0 = kv0 + ((lane & 3) << 1);
            if (kv0 + 63 > wrow) {
#pragma unroll
                for (int nb = 0; nb < 8; nb++) {
                    const int c = c0 + nb * 8;
                    if (c     > r0    ) s[nb][0] = -1e30f;
                    if (c + 1 > r0    ) s[nb][1] = -1e30f;
                    if (c     > r0 + 8) s[nb][2] = -1e30f;
                    if (c + 1 > r0 + 8) s[nb][3] = -1e30f;
                }
            }

            float tm0 = -1e30f, tm1 = -1e30f;
#pragma unroll
            for (int nb = 0; nb < 8; nb++) {
                tm0 = fmaxf(tm0, fmaxf(s[nb][0], s[nb][1]));
                tm1 = fmaxf(tm1, fmaxf(s[nb][2], s[nb][3]));
            }
            tm0 = fmaxf(tm0, __shfl_xor_sync(0xffffffffu, tm0, 1));
            tm0 = fmaxf(tm0, __shfl_xor_sync(0xffffffffu, tm0, 2));
            tm1 = fmaxf(tm1, __shfl_xor_sync(0xffffffffu, tm1, 1));
            tm1 = fmaxf(tm1, __shfl_xor_sync(0xffffffffu, tm1, 2));
            const float mn0 = fmaxf(mr0, tm0), mn1 = fmaxf(mr1, tm1);
            const float sf0 = exp2f((mr0 - mn0) * FC);
            const float sf1 = exp2f((mr1 - mn1) * FC);
            mr0 = mn0; mr1 = mn1;
            l0 *= sf0;  l1 *= sf1;
#pragma unroll
            for (int nb = 0; nb < 16; nb++) {
                o[nb][0] *= sf0; o[nb][1] *= sf0;
                o[nb][2] *= sf1; o[nb][3] *= sf1;
            }
            float rs0 = 0.f, rs1 = 0.f;
#pragma unroll
            for (int nb = 0; nb < 8; nb++) {
                s[nb][0] = exp2f((s[nb][0] - mn0) * FC); rs0 += s[nb][0];
                s[nb][1] = exp2f((s[nb][1] - mn0) * FC); rs0 += s[nb][1];
                s[nb][2] = exp2f((s[nb][2] - mn1) * FC); rs1 += s[nb][2];
                s[nb][3] = exp2f((s[nb][3] - mn1) * FC); rs1 += s[nb][3];
            }
            rs0 += __shfl_xor_sync(0xffffffffu, rs0, 1);
            rs0 += __shfl_xor_sync(0xffffffffu, rs0, 2);
            rs1 += __shfl_xor_sync(0xffffffffu, rs1, 1);
            rs1 += __shfl_xor_sync(0xffffffffu, rs1, 2);
            l0 += rs0; l1 += rs1;

#pragma unroll
            for (int j = 0; j < 4; j++) {
                uint32_t pha[4];
#pragma unroll
                for (int hq = 0; hq < 4; hq++) {
                    const int nb = 2 * j + (hq >> 1);
                    const int e  = (hq & 1) << 1;
                    __half2 h = __floats2half2_rn(s[nb][e], s[nb][e + 1]);
                    pha[hq] = *reinterpret_cast<uint32_t*>(&h);
                }
#pragma unroll
                for (int g16 = 0; g16 < 8; g16++) {
                    uint32_t bh[4];
                    const uint32_t ba = (uint32_t)(g16 * 16 + brow) * 144 + bko + j * 32;
                    LDSM4(bh[0], bh[1], bh[2], bh[3], vb_h + ba);
                    MMA16816(o[2 * g16],     pha, bh);
                    MMA16816(o[2 * g16 + 1], pha, bh + 2);
                }
            }
        }
        __syncthreads();
        buf ^= 1;
    }

    const float inv0 = 1.f / l0, inv1 = 1.f / l1;
    const int r0 = wrow + (lane >> 2);
    const long base0 = ((long)z * SEQ + r0) * HD + ((lane & 3) << 1);
    const long base1 = base0 + 8 * HD;
#pragma unroll
    for (int nb = 0; nb < 16; nb++) {
        *(__half2*)(oah + base0 + nb * 8) =
            __floats2half2_rn(o[nb][0] * inv0, o[nb][1] * inv0);
        *(__half2*)(oah + base1 + nb * 8) =
            __floats2half2_rn(o[nb][2] * inv1, o[nb][3] * inv1);
    }
}

// ---------------- prep: rope table + weight cvt in one launch ----------------
#define TAB_BLKS 512
__global__ __launch_bounds__(256)
void prep_k(const int* __restrict__ pos, float2* __restrict__ tab,
            const float* __restrict__ qw, const float* __restrict__ kw,
            const float* __restrict__ vw, const float* __restrict__ ow,
            __half* __restrict__ d)
{
    const int bid = blockIdx.x;
    if (bid < TAB_BLKS) {
        int idx = bid * 256 + threadIdx.x;
        if (idx >= SEQ * 64) return;
        int i = idx & 63;
        int l = idx >> 6;
        float invf = exp2f(-(float)i * 0.31143075889569023f);
        float ang  = (float)pos[l] * invf;
        float q  = rintf(ang * 0.15915494309189535f);
        float r  = ang - q * 6.28125f;
        r        = r   - q * 1.9353071795864769e-3f;
        float s, c;
        sincosf(r, &s, &c);
        tab[idx] = make_float2(c, s);
        return;
    }
    int e = ((bid - TAB_BLKS) * 256 + threadIdx.x) << 2;
    if (e >= W_TOT) return;
    const float* s;
    if      (e < KW_OFF) s = qw + e;
    else if (e < VW_OFF) s = kw + (e - KW_OFF);
    else if (e < OW_OFF) s = vw + (e - VW_OFF);
    else                 s = ow + (e - OW_OFF);
    float4 v = *(const float4*)s;
    ((__half2*)(d + e))[0] = __floats2half2_rn(v.x, v.y);
    ((__half2*)(d + e))[1] = __floats2half2_rn(v.z, v.w);
}

// ---------------- launch ----------------
extern "C" void kernel_launch(void* const* d_in, const int* in_sizes, int n_in,
                              void* d_out, int out_size)
{
    const float* qhid = (const float*)d_in[0];
    const float* khid = (const float*)d_in[1];
    const float* vhid = (const float*)d_in[2];
    const int*   pos  = (const int*)  d_in[4];
    const float* qw   = (const float*)d_in[5];
    const float* kw   = (const float*)d_in[6];
    const float* vw   = (const float*)d_in[7];
    const float* ow   = (const float*)d_in[8];
    float*       out  = (float*)d_out;

    __half *qhh, *khh, *vth, *ahh, *wh;
    float2* tab;
    cudaGetSymbolAddress((void**)&qhh, g_qh);
    cudaGetSymbolAddress((void**)&khh, g_kh);
    cudaGetSymbolAddress((void**)&vth, g_vth);
    cudaGetSymbolAddress((void**)&ahh, g_ah);
    cudaGetSymbolAddress((void**)&wh,  g_wh);
    cudaGetSymbolAddress((void**)&tab, g_tab);

    cudaFuncSetAttribute(proj_k,  cudaFuncAttributeMaxDynamicSharedMemorySize, PSMB);
    cudaFuncSetAttribute(oproj_k, cudaFuncAttributeMaxDynamicSharedMemorySize, OSMB);
    cudaFuncSetAttribute(flash_k, cudaFuncAttributeMaxDynamicSharedMemorySize, FSMEM);

    // rope table + f16 weights in one launch
    prep_k<<<TAB_BLKS + (W_TOT / 4 + 255) / 256, 256>>>(pos, tab, qw, kw, vw, ow, wh);

    // Q+K+V projections, fused RoPE / V-transpose / f16 epilogues; M-tile 64
    proj_k<<<dim3(1, 32, NH + 2 * NKV), 256, PSMB>>>(qhid, khid, vhid, wh, tab);

    // fused attention -> attn f16
    flash_k<<<dim3(NH, 32), 128, FSMEM>>>(qhh, khh, vth, ahh);

    // O projection: one-shot K=128
    oproj_k<<<dim3(16, 16, NH), 256, OSMB>>>(ahh, wh + OW_OFF, out);
}